// round 8
// baseline (speedup 1.0000x reference)
#include <cuda_runtime.h>
#include <cuda_fp16.h>
#include <cstdint>

#define NN 100000
#define EE 1600000
#define F 64
#define SCAN_B 1024
#define MAXPB 128   // ceil(NN/1024) = 98 <= 128

// ---------------- device scratch (static: allocation-guard safe) ----------------
__device__ int   g_cnt_row[NN];
__device__ int   g_cnt_col[NN];
__device__ int   g_row_off[NN + 1];
__device__ int   g_col_off[NN + 1];
__device__ int   g_cur_row[NN];
__device__ int   g_cur_col[NN];
__device__ int   g_part[2][MAXPB];
__device__ int   g_partscan[2][MAXPB + 1];
__device__ int   g_csr_col[EE];
__device__ int   g_csc_row[EE];
__device__ float g_Avdin[NN], g_Avdout[NN], g_Atvdout[NN], g_Atvdin[NN];
__device__ float4 g_preA[NN];     // {isi, sAtA, sAAi, 0}
__device__ float4 g_preT[NN];     // {iso, sAAt, sAAo, 0}
__device__ float g_post[6][NN];   // 0:iso 1:isi 2:sAAt 3:sAtA 4:sAAo 5:sAAi
__device__ __half g_xh[(size_t)NN * F];
__device__ __half g_uw[(size_t)NN * 128];   // [u | w]
__device__ __half g_vz[(size_t)NN * 128];   // [v | z]
__device__ __half g_Hh[6][(size_t)NN * F];
__device__ __half g_Whi[6][4096];           // W hi fp16, transposed [n][k], linear
__device__ __half g_Wlo[6][4096];           // W lo residual, [n][k], linear
__device__ float  g_bsum[64];               // sum of 6 biases

// ---------------- x -> fp16 copy, fused with counter zeroing ----------------
__global__ void k_xhalf(const float* __restrict__ x, int total32, int n) {
    int i = blockIdx.x * blockDim.x + threadIdx.x;
    if (i < n) { g_cnt_row[i] = 0; g_cnt_col[i] = 0; }
    if (i < total32) {
        float2 f = __ldg((const float2*)x + i);
        *((__half2*)g_xh + i) = __floats2half2_rn(f.x, f.y);
    }
}

// ---------------- W split + bias sum precompute (once, tiny) -----------------
__global__ void k_wsplit(const float* __restrict__ W0, const float* __restrict__ W1,
                         const float* __restrict__ W2, const float* __restrict__ W3,
                         const float* __restrict__ W4, const float* __restrict__ W5,
                         const float* __restrict__ B0, const float* __restrict__ B1,
                         const float* __restrict__ B2, const float* __restrict__ B3,
                         const float* __restrict__ B4, const float* __restrict__ B5) {
    const float* Ws[6] = {W0, W1, W2, W3, W4, W5};
    int idx = blockIdx.x * blockDim.x + threadIdx.x;
    if (idx < 6 * 4096) {
        int m = idx >> 12;
        int r = idx & 4095;          // r = k*64 + nn in source
        int k = r >> 6;
        int nn = r & 63;
        float wv = __ldg(Ws[m] + r);
        __half hi = __float2half_rn(wv);
        __half lo = __float2half_rn(wv - __half2float(hi));
        g_Whi[m][nn * 64 + k] = hi;  // transposed [n][k]
        g_Wlo[m][nn * 64 + k] = lo;
    }
    if (blockIdx.x == 0 && threadIdx.x < 64) {
        const float* Bs[6] = {B0, B1, B2, B3, B4, B5};
        float s = 0.f;
#pragma unroll
        for (int m = 0; m < 6; m++) s += __ldg(Bs[m] + threadIdx.x);
        g_bsum[threadIdx.x] = s;
    }
}

__global__ void k_hist(const int* __restrict__ ei, int E) {
    int e = blockIdx.x * blockDim.x + threadIdx.x;
    if (e < E) {
        atomicAdd(&g_cnt_row[ei[e]], 1);
        atomicAdd(&g_cnt_col[ei[E + e]], 1);
    }
}

// -------- scan phase 1: per-block partial sums (warp-shuffle reduce) ---------
__global__ void k_scan_part(int n) {
    int dir = blockIdx.y;
    const int* cnt = dir ? g_cnt_col : g_cnt_row;
    int tid = threadIdx.x;
    int base = blockIdx.x * SCAN_B;
    int s = 0;
#pragma unroll
    for (int j = 0; j < 4; j++) {
        int i = base + tid + j * 256;
        if (i < n) s += cnt[i];
    }
#pragma unroll
    for (int d = 16; d > 0; d >>= 1) s += __shfl_down_sync(0xffffffffu, s, d);
    __shared__ int ws[8];
    if ((tid & 31) == 0) ws[tid >> 5] = s;
    __syncthreads();
    if (tid == 0) {
        int v = 0;
#pragma unroll
        for (int j = 0; j < 8; j++) v += ws[j];
        g_part[dir][blockIdx.x] = v;
    }
}

// -------- scan phase 2: one block, warp-shuffle scan of <=128 partials -------
__global__ void k_scan_mid(int pb) {
    __shared__ int ws[4];
    int tid = threadIdx.x;
    int lane = tid & 31, wd = tid >> 5;
    for (int dir = 0; dir < 2; dir++) {
        int v = (tid < pb) ? g_part[dir][tid] : 0;
        int incl = v;
#pragma unroll
        for (int d = 1; d < 32; d <<= 1) {
            int t = __shfl_up_sync(0xffffffffu, incl, d);
            if (lane >= d) incl += t;
        }
        if (lane == 31) ws[wd] = incl;
        __syncthreads();
        int basev = 0;
#pragma unroll
        for (int k = 0; k < 4; k++) if (k < wd) basev += ws[k];
        int total = ws[0] + ws[1] + ws[2] + ws[3];
        if (tid < pb) g_partscan[dir][tid] = basev + incl - v;   // exclusive
        if (tid == 0) g_partscan[dir][pb] = total;
        __syncthreads();
    }
}

// -------- scan phase 3: per-block warp-shuffle scan + base; init cursors -----
__global__ void k_scan_final(int n, int pb) {
    int dir = blockIdx.y;
    const int* cnt = dir ? g_cnt_col : g_cnt_row;
    int* off = dir ? g_col_off : g_row_off;
    int* cur = dir ? g_cur_col : g_cur_row;
    __shared__ int ws[32];
    int tid = threadIdx.x;
    int lane = tid & 31, wd = tid >> 5;
    int i = blockIdx.x * SCAN_B + tid;
    int v = (i < n) ? cnt[i] : 0;
    int incl = v;
#pragma unroll
    for (int d = 1; d < 32; d <<= 1) {
        int t = __shfl_up_sync(0xffffffffu, incl, d);
        if (lane >= d) incl += t;
    }
    if (lane == 31) ws[wd] = incl;
    __syncthreads();
    if (wd == 0) {
        int t = ws[lane];
#pragma unroll
        for (int d = 1; d < 32; d <<= 1) {
            int u = __shfl_up_sync(0xffffffffu, t, d);
            if (lane >= d) t += u;
        }
        ws[lane] = t;
    }
    __syncthreads();
    int wbase = (wd > 0) ? ws[wd - 1] : 0;
    if (i < n) {
        int o = g_partscan[dir][blockIdx.x] + wbase + incl - v;
        off[i] = o;
        cur[i] = o;
    }
    if (blockIdx.x == 0 && tid == 0) off[n] = g_partscan[dir][pb];
}

__global__ void k_scatter(const int* __restrict__ ei, int E) {
    int e = blockIdx.x * blockDim.x + threadIdx.x;
    if (e < E) {
        int r = ei[e], c = ei[E + e];
        int p = atomicAdd(&g_cur_row[r], 1);
        g_csr_col[p] = c;
        int q = atomicAdd(&g_cur_col[c], 1);
        g_csc_row[q] = r;
    }
}

// ---------------- scalar degree SpMVs, MLP-4 unrolled (round-6 form) ---------
__global__ void k_degspmv(int n) {
    int dir = blockIdx.y;
    int i = blockIdx.x * blockDim.x + threadIdx.x;
    if (i >= n) return;
    const int* off = dir ? g_col_off : g_row_off;
    const int* nbr = dir ? g_csc_row : g_csr_col;
    const int* cA  = dir ? g_cnt_row : g_cnt_col;
    const int* cB  = dir ? g_cnt_col : g_cnt_row;
    float* oA = dir ? g_Atvdout : g_Avdin;
    float* oB = dir ? g_Atvdin  : g_Avdout;
    int s = off[i], e = off[i + 1];
    int sa = 0, sb = 0;
    int j = s;
    for (; j + 4 <= e; j += 4) {
        int n0 = __ldg(nbr + j + 0);
        int n1 = __ldg(nbr + j + 1);
        int n2 = __ldg(nbr + j + 2);
        int n3 = __ldg(nbr + j + 3);
        int a0 = __ldg(cA + n0), b0 = __ldg(cB + n0);
        int a1 = __ldg(cA + n1), b1 = __ldg(cB + n1);
        int a2 = __ldg(cA + n2), b2 = __ldg(cB + n2);
        int a3 = __ldg(cA + n3), b3 = __ldg(cB + n3);
        sa += (a0 + a1) + (a2 + a3);
        sb += (b0 + b1) + (b2 + b3);
    }
    for (; j < e; j++) {
        int nb = __ldg(nbr + j);
        sa += __ldg(cA + nb);
        sb += __ldg(cB + nb);
    }
    oA[i] = (float)sa;
    oB[i] = (float)sb;
}

__device__ __forceinline__ float invsq(float d) {
    return d > 0.f ? 1.0f / sqrtf(d) : 0.0f;
}

__global__ void k_scales(int n) {
    int i = blockIdx.x * blockDim.x + threadIdx.x;
    if (i >= n) return;
    float iso  = invsq((float)g_cnt_row[i]);
    float isi  = invsq((float)g_cnt_col[i]);
    float sAAt = invsq(g_Avdin[i]);
    float sAtA = invsq(g_Atvdout[i]);
    float sAAo = invsq(g_Avdout[i]);
    float sAAi = invsq(g_Atvdin[i]);
    g_preA[i] = make_float4(isi, sAtA, sAAi, 0.f);
    g_preT[i] = make_float4(iso, sAAt, sAAo, 0.f);
    g_post[0][i] = iso;  g_post[1][i] = isi;
    g_post[2][i] = sAAt; g_post[3][i] = sAtA;
    g_post[4][i] = sAAo; g_post[5][i] = sAAi;
}

// ---------------- round-1 fused SpMM over fp16 x: MLP-4 batched gather -------
__global__ void k_spmm3(int n) {
    int dir = blockIdx.y;
    int gw = (blockIdx.x * blockDim.x + threadIdx.x) >> 5;
    int lane = threadIdx.x & 31;
    if (gw >= n) return;
    const int* off = dir ? g_col_off : g_row_off;
    const int* nbr = dir ? g_csc_row : g_csr_col;
    const float4* pre = dir ? g_preT : g_preA;
    const float* post0 = dir ? g_post[1] : g_post[0];
    __half* out0 = g_Hh[dir];
    __half* out1 = dir ? g_uw : g_vz;
    __half* out2 = dir ? g_vz : g_uw;
    const uint32_t* xw = (const uint32_t*)g_xh;

    int s = off[gw], e = off[gw + 1];
    float a0x = 0.f, a0y = 0.f, a1x = 0.f, a1y = 0.f, a2x = 0.f, a2y = 0.f;
    for (int base = s; base < e; base += 32) {
        int idx = base + lane;
        int myn = 0;
        float4 mp = make_float4(0.f, 0.f, 0.f, 0.f);
        if (idx < e) {
            myn = __ldg(nbr + idx);
            mp = __ldg(pre + myn);
        }
        int cnt = min(32, e - base);
        for (int k = 0; k < cnt; k += 4) {
            int nd[4]; float p0[4], p1[4], p2[4]; uint32_t raw[4];
#pragma unroll
            for (int j = 0; j < 4; j++) {
                int kk = k + j;
                nd[j] = __shfl_sync(0xffffffffu, myn, kk);
                p0[j] = __shfl_sync(0xffffffffu, mp.x, kk);
                p1[j] = __shfl_sync(0xffffffffu, mp.y, kk);
                p2[j] = __shfl_sync(0xffffffffu, mp.z, kk);
            }
#pragma unroll
            for (int j = 0; j < 4; j++)
                raw[j] = __ldg(xw + (size_t)nd[j] * 32 + lane);
#pragma unroll
            for (int j = 0; j < 4; j++) {
                float2 f = __half22float2(*reinterpret_cast<__half2*>(&raw[j]));
                a0x = fmaf(p0[j], f.x, a0x); a0y = fmaf(p0[j], f.y, a0y);
                a1x = fmaf(p1[j], f.x, a1x); a1y = fmaf(p1[j], f.y, a1y);
                a2x = fmaf(p2[j], f.x, a2x); a2y = fmaf(p2[j], f.y, a2y);
            }
        }
    }
    float pp = post0[gw];
    *(__half2*)(out0 + (size_t)gw * F + lane * 2) = __floats2half2_rn(pp * a0x, pp * a0y);
    *(__half2*)(out1 + (size_t)gw * 128 + lane * 2) = __floats2half2_rn(a1x, a1y);
    *(__half2*)(out2 + (size_t)gw * 128 + 64 + lane * 2) = __floats2half2_rn(a2x, a2y);
}

// ---------------- round-2 fused SpMM: MLP-4 batched 256B gathers -------------
__global__ void k_spmm2(int n) {
    int dir = blockIdx.y;
    int gw = (blockIdx.x * blockDim.x + threadIdx.x) >> 5;
    int lane = threadIdx.x & 31;
    if (gw >= n) return;
    const int* off = dir ? g_col_off : g_row_off;
    const int* nbr = dir ? g_csc_row : g_csr_col;
    const uint2* in = (const uint2*)(dir ? g_vz : g_uw);

    int s = off[gw], e = off[gw + 1];
    float a0 = 0.f, a1 = 0.f, a2 = 0.f, a3 = 0.f;
    for (int base = s; base < e; base += 32) {
        int idx = base + lane;
        int myn = 0;
        float wt = 0.f;
        if (idx < e) { myn = __ldg(nbr + idx); wt = 1.f; }
        int cnt = min(32, e - base);
        for (int k = 0; k < cnt; k += 4) {
            int nd[4]; float wj[4]; uint2 raw[4];
#pragma unroll
            for (int j = 0; j < 4; j++) {
                int kk = k + j;
                nd[j] = __shfl_sync(0xffffffffu, myn, kk);
                wj[j] = __shfl_sync(0xffffffffu, wt, kk);
            }
#pragma unroll
            for (int j = 0; j < 4; j++)
                raw[j] = __ldg(in + (size_t)nd[j] * 32 + lane);
#pragma unroll
            for (int j = 0; j < 4; j++) {
                float2 f0 = __half22float2(*reinterpret_cast<__half2*>(&raw[j].x));
                float2 f1 = __half22float2(*reinterpret_cast<__half2*>(&raw[j].y));
                a0 = fmaf(wj[j], f0.x, a0); a1 = fmaf(wj[j], f0.y, a1);
                a2 = fmaf(wj[j], f1.x, a2); a3 = fmaf(wj[j], f1.y, a3);
            }
        }
    }
    bool partA = lane < 16;
    const float* post = dir ? (partA ? g_post[3] : g_post[5])
                            : (partA ? g_post[2] : g_post[4]);
    __half* outH = dir ? (partA ? g_Hh[3] : g_Hh[5])
                       : (partA ? g_Hh[2] : g_Hh[4]);
    float p = post[gw];
    int fbase = (lane & 15) * 4;
    __half2 o0 = __floats2half2_rn(p * a0, p * a1);
    __half2 o1 = __floats2half2_rn(p * a2, p * a3);
    uint2 st;
    st.x = *reinterpret_cast<uint32_t*>(&o0);
    st.y = *reinterpret_cast<uint32_t*>(&o1);
    *(uint2*)(outH + (size_t)gw * F + fbase) = st;
}

// ---------------- fp16 HMMA GEMM: smem W from precomputed hi/lo --------------
__device__ __forceinline__ void mma_f16(float* c, uint32_t a0, uint32_t a1,
                                        uint32_t a2, uint32_t a3,
                                        uint32_t b0, uint32_t b1) {
    asm volatile(
        "mma.sync.aligned.m16n8k16.row.col.f32.f16.f16.f32 "
        "{%0,%1,%2,%3}, {%4,%5,%6,%7}, {%8,%9}, {%0,%1,%2,%3};"
        : "+f"(c[0]), "+f"(c[1]), "+f"(c[2]), "+f"(c[3])
        : "r"(a0), "r"(a1), "r"(a2), "r"(a3), "r"(b0), "r"(b1));
}

#define LDH 72   // padded half stride: conflict-free (4g+t) fragment loads

__global__ __launch_bounds__(256, 2) void k_gemm(float* __restrict__ out, int n) {
    __shared__ __half sH[64 * LDH];     // H tile [row][k]
    __shared__ __half sWhi[64 * LDH];   // W hi [n][k] padded
    __shared__ __half sWlo[64 * LDH];   // W lo [n][k] padded

    int tid = threadIdx.x;
    int rowBase = blockIdx.x * 64;
    int w = tid >> 5;
    int lane = tid & 31;
    int g = lane >> 2;
    int t = lane & 3;
    int wr = (w & 1) * 32;
    int wc = (w >> 1) * 16;

    float acc[2][2][4];
#pragma unroll
    for (int i = 0; i < 2; i++)
#pragma unroll
        for (int j = 0; j < 2; j++)
#pragma unroll
            for (int q = 0; q < 4; q++) acc[i][j][q] = 0.f;

#pragma unroll
    for (int m = 0; m < 6; m++) {
        const __half* Hm = g_Hh[m];
        // H tile: 64 rows x 64 halves = 1024 uint2
#pragma unroll
        for (int it = 0; it < 4; it++) {
            int idx = tid + it * 256;
            int r = idx >> 4;
            int c4 = (idx & 15) << 2;
            int gr = rowBase + r;
            uint2 raw = make_uint2(0u, 0u);
            if (gr < n) raw = __ldg((const uint2*)(Hm) + (size_t)gr * 16 + (idx & 15));
            *(uint2*)(&sH[r * LDH + c4]) = raw;
        }
        // W hi/lo: 512 uint4 each, straight copy into padded layout
#pragma unroll
        for (int it = 0; it < 2; it++) {
            int idx = tid + it * 256;            // uint4 index (8 halves)
            int nn = idx >> 3;
            int k8 = (idx & 7) << 3;
            uint4 hv = __ldg((const uint4*)(g_Whi[m]) + idx);
            uint4 lv = __ldg((const uint4*)(g_Wlo[m]) + idx);
            *(uint4*)(&sWhi[nn * LDH + k8]) = hv;
            *(uint4*)(&sWlo[nn * LDH + k8]) = lv;
        }
        __syncthreads();

#pragma unroll
        for (int kk = 0; kk < 64; kk += 16) {
            uint32_t a[2][4];
#pragma unroll
            for (int mt = 0; mt < 2; mt++) {
                int rbase = wr + mt * 16;
                a[mt][0] = *(const uint32_t*)(&sH[(rbase + g) * LDH + kk + 2 * t]);
                a[mt][1] = *(const uint32_t*)(&sH[(rbase + g + 8) * LDH + kk + 2 * t]);
                a[mt][2] = *(const uint32_t*)(&sH[(rbase + g) * LDH + kk + 2 * t + 8]);
                a[mt][3] = *(const uint32_t*)(&sH[(rbase + g + 8) * LDH + kk + 2 * t + 8]);
            }
            uint32_t bh[2][2], bl[2][2];
#pragma unroll
            for (int nt = 0; nt < 2; nt++) {
                int nbase = wc + nt * 8;
                bh[nt][0] = *(const uint32_t*)(&sWhi[(nbase + g) * LDH + kk + 2 * t]);
                bh[nt][1] = *(const uint32_t*)(&sWhi[(nbase + g) * LDH + kk + 2 * t + 8]);
                bl[nt][0] = *(const uint32_t*)(&sWlo[(nbase + g) * LDH + kk + 2 * t]);
                bl[nt][1] = *(const uint32_t*)(&sWlo[(nbase + g) * LDH + kk + 2 * t + 8]);
            }
#pragma unroll
            for (int mt = 0; mt < 2; mt++)
#pragma unroll
                for (int nt = 0; nt < 2; nt++) {
                    mma_f16(acc[mt][nt], a[mt][0], a[mt][1], a[mt][2], a[mt][3],
                            bl[nt][0], bl[nt][1]);
                    mma_f16(acc[mt][nt], a[mt][0], a[mt][1], a[mt][2], a[mt][3],
                            bh[nt][0], bh[nt][1]);
                }
        }
        __syncthreads();
    }

#pragma unroll
    for (int mt = 0; mt < 2; mt++) {
#pragma unroll
        for (int nt = 0; nt < 2; nt++) {
            int col = wc + nt * 8 + 2 * t;
            float bx = __ldg(&g_bsum[col]);
            float by = __ldg(&g_bsum[col + 1]);
            int r1 = rowBase + wr + mt * 16 + g;
            int r2 = r1 + 8;
            if (r1 < n) {
                float2 o;
                o.x = 0.75f * (acc[mt][nt][0] + bx);
                o.y = 0.75f * (acc[mt][nt][1] + by);
                *(float2*)(out + (size_t)r1 * 64 + col) = o;
            }
            if (r2 < n) {
                float2 o;
                o.x = 0.75f * (acc[mt][nt][2] + bx);
                o.y = 0.75f * (acc[mt][nt][3] + by);
                *(float2*)(out + (size_t)r2 * 64 + col) = o;
            }
        }
    }
}

// ---------------- launcher ----------------
extern "C" void kernel_launch(void* const* d_in, const int* in_sizes, int n_in,
                              void* d_out, int out_size) {
    const float* x = (const float*)d_in[0];
    const int* ei = (const int*)d_in[1];
    const float* W0 = (const float*)d_in[2],  *B0 = (const float*)d_in[3];
    const float* W1 = (const float*)d_in[4],  *B1 = (const float*)d_in[5];
    const float* W2 = (const float*)d_in[6],  *B2 = (const float*)d_in[7];
    const float* W3 = (const float*)d_in[8],  *B3 = (const float*)d_in[9];
    const float* W4 = (const float*)d_in[10], *B4 = (const float*)d_in[11];
    const float* W5 = (const float*)d_in[12], *B5 = (const float*)d_in[13];
    float* out = (float*)d_out;

    int n = in_sizes[0] / F;
    int E = in_sizes[1] / 2;
    if (n > NN) n = NN;
    if (E > EE) E = EE;

    int nb = (n + 255) / 256;
    int eb = (E + 255) / 256;
    int pb = (n + SCAN_B - 1) / SCAN_B;
    int xw = n * 32;                       // half2 words in x

    k_xhalf<<<(xw + 255) / 256, 256>>>(x, xw, n);
    k_wsplit<<<96, 256>>>(W0, W1, W2, W3, W4, W5, B0, B1, B2, B3, B4, B5);
    k_hist<<<eb, 256>>>(ei, E);
    k_scan_part<<<dim3(pb, 2), 256>>>(n);
    k_scan_mid<<<1, 128>>>(pb);
    k_scan_final<<<dim3(pb, 2), SCAN_B>>>(n, pb);
    k_scatter<<<eb, 256>>>(ei, E);
    k_degspmv<<<dim3(nb, 2), 256>>>(n);
    k_scales<<<nb, 256>>>(n);

    int sb = (n + 7) / 8;   // warp-per-node, 8 warps/block
    k_spmm3<<<dim3(sb, 2), 256>>>(n);
    k_spmm2<<<dim3(sb, 2), 256>>>(n);

    int gb = (n + 63) / 64;
    k_gemm<<<gb, 256>>>(out, n);
}

// round 9
// speedup vs baseline: 1.3210x; 1.3210x over previous
#include <cuda_runtime.h>
#include <cuda_fp16.h>
#include <cstdint>

#define NN 100000
#define EE 1600000
#define F 64
#define SCAN_B 1024
#define MAXPB 128   // ceil(NN/1024) = 98 <= 128

// ---------------- device scratch (static: allocation-guard safe) ----------------
__device__ int   g_cnt_row[NN];
__device__ int   g_cnt_col[NN];
__device__ int   g_row_off[NN + 1];
__device__ int   g_col_off[NN + 1];
__device__ int   g_cur_row[NN];
__device__ int   g_cur_col[NN];
__device__ int   g_part[2][MAXPB];
__device__ int   g_partscan[2][MAXPB + 1];
__device__ int   g_csr_col[EE];   // neighbors (col ids) grouped by row  -> Av
__device__ int   g_csc_row[EE];   // neighbors (row ids) grouped by col  -> Atv
__device__ float g_Avdin[NN], g_Avdout[NN], g_Atvdout[NN], g_Atvdin[NN];
__device__ float4 g_preA[NN];     // {isi, sAtA, sAAi, 0} pre-scales for round-1 Av
__device__ float4 g_preT[NN];     // {iso, sAAt, sAAo, 0} pre-scales for round-1 Atv
__device__ float g_post[6][NN];   // 0:iso 1:isi 2:sAAt 3:sAtA 4:sAAo 5:sAAi
__device__ __half g_xh[(size_t)NN * F];     // fp16 copy of x (128B/row)
__device__ __half g_uw[(size_t)NN * 128];   // [u | w]
__device__ __half g_vz[(size_t)NN * 128];   // [v | z]
__device__ __half g_Hh[6][(size_t)NN * F];  // A_x, At_x, AAt_x, AtA_x, AA_x, AtAt_x

// ---------------- x -> fp16 copy, fused with counter zeroing ----------------
__global__ void k_xhalf(const float* __restrict__ x, int total32, int n) {
    int i = blockIdx.x * blockDim.x + threadIdx.x;
    if (i < n) { g_cnt_row[i] = 0; g_cnt_col[i] = 0; }
    if (i < total32) {
        float2 f = __ldg((const float2*)x + i);
        *((__half2*)g_xh + i) = __floats2half2_rn(f.x, f.y);
    }
}

__global__ void k_hist(const int* __restrict__ ei, int E) {
    int e = blockIdx.x * blockDim.x + threadIdx.x;
    if (e < E) {
        atomicAdd(&g_cnt_row[ei[e]], 1);
        atomicAdd(&g_cnt_col[ei[E + e]], 1);
    }
}

// -------- multi-block exclusive scan: phase 1, per-block partial sums --------
__global__ void k_scan_part(int n) {
    int dir = blockIdx.y;
    const int* cnt = dir ? g_cnt_col : g_cnt_row;
    __shared__ int sh[256];
    int tid = threadIdx.x;
    int base = blockIdx.x * SCAN_B;
    int s = 0;
#pragma unroll
    for (int j = 0; j < 4; j++) {
        int i = base + tid + j * 256;
        if (i < n) s += cnt[i];
    }
    sh[tid] = s;
    __syncthreads();
    for (int d = 128; d > 0; d >>= 1) {
        if (tid < d) sh[tid] += sh[tid + d];
        __syncthreads();
    }
    if (tid == 0) g_part[dir][blockIdx.x] = sh[0];
}

// -------- phase 2: single block scans the <=128 partials for both dirs -------
__global__ void k_scan_mid(int pb) {
    __shared__ int sh[128];
    int tid = threadIdx.x;
    for (int dir = 0; dir < 2; dir++) {
        int v = (tid < pb) ? g_part[dir][tid] : 0;
        sh[tid] = v;
        __syncthreads();
        for (int d = 1; d < 128; d <<= 1) {
            int add = (tid >= d) ? sh[tid - d] : 0;
            __syncthreads();
            sh[tid] += add;
            __syncthreads();
        }
        if (tid < pb) g_partscan[dir][tid] = sh[tid] - v;   // exclusive
        if (tid == 0) g_partscan[dir][pb] = sh[127];        // total
        __syncthreads();
    }
}

// -------- phase 3: per-block scan + base; also init scatter cursors ----------
__global__ void k_scan_final(int n, int pb) {
    int dir = blockIdx.y;
    const int* cnt = dir ? g_cnt_col : g_cnt_row;
    int* off = dir ? g_col_off : g_row_off;
    int* cur = dir ? g_cur_col : g_cur_row;
    __shared__ int sh[SCAN_B];
    int tid = threadIdx.x;
    int i = blockIdx.x * SCAN_B + tid;
    int v = (i < n) ? cnt[i] : 0;
    sh[tid] = v;
    __syncthreads();
    for (int d = 1; d < SCAN_B; d <<= 1) {
        int add = (tid >= d) ? sh[tid - d] : 0;
        __syncthreads();
        sh[tid] += add;
        __syncthreads();
    }
    if (i < n) {
        int o = g_partscan[dir][blockIdx.x] + sh[tid] - v;  // exclusive
        off[i] = o;
        cur[i] = o;
    }
    if (blockIdx.x == 0 && tid == 0) off[n] = g_partscan[dir][pb];
}

__global__ void k_scatter(const int* __restrict__ ei, int E) {
    int e = blockIdx.x * blockDim.x + threadIdx.x;
    if (e < E) {
        int r = ei[e], c = ei[E + e];
        int p = atomicAdd(&g_cur_row[r], 1);
        g_csr_col[p] = c;
        int q = atomicAdd(&g_cur_col[c], 1);
        g_csc_row[q] = r;
    }
}

// ---------------- scalar degree SpMVs, MLP-4 unrolled -------------------------
__global__ void k_degspmv(int n) {
    int dir = blockIdx.y;
    int i = blockIdx.x * blockDim.x + threadIdx.x;
    if (i >= n) return;
    const int* off = dir ? g_col_off : g_row_off;
    const int* nbr = dir ? g_csc_row : g_csr_col;
    const int* cA  = dir ? g_cnt_row : g_cnt_col;
    const int* cB  = dir ? g_cnt_col : g_cnt_row;
    float* oA = dir ? g_Atvdout : g_Avdin;
    float* oB = dir ? g_Atvdin  : g_Avdout;
    int s = off[i], e = off[i + 1];
    int sa = 0, sb = 0;
    int j = s;
    for (; j + 4 <= e; j += 4) {
        int n0 = __ldg(nbr + j + 0);
        int n1 = __ldg(nbr + j + 1);
        int n2 = __ldg(nbr + j + 2);
        int n3 = __ldg(nbr + j + 3);
        int a0 = __ldg(cA + n0), b0 = __ldg(cB + n0);
        int a1 = __ldg(cA + n1), b1 = __ldg(cB + n1);
        int a2 = __ldg(cA + n2), b2 = __ldg(cB + n2);
        int a3 = __ldg(cA + n3), b3 = __ldg(cB + n3);
        sa += (a0 + a1) + (a2 + a3);
        sb += (b0 + b1) + (b2 + b3);
    }
    for (; j < e; j++) {
        int nb = __ldg(nbr + j);
        sa += __ldg(cA + nb);
        sb += __ldg(cB + nb);
    }
    oA[i] = (float)sa;
    oB[i] = (float)sb;
}

__device__ __forceinline__ float invsq(float d) {
    return d > 0.f ? 1.0f / sqrtf(d) : 0.0f;
}

__global__ void k_scales(int n) {
    int i = blockIdx.x * blockDim.x + threadIdx.x;
    if (i >= n) return;
    float iso  = invsq((float)g_cnt_row[i]);
    float isi  = invsq((float)g_cnt_col[i]);
    float sAAt = invsq(g_Avdin[i]);
    float sAtA = invsq(g_Atvdout[i]);
    float sAAo = invsq(g_Avdout[i]);
    float sAAi = invsq(g_Atvdin[i]);
    g_preA[i] = make_float4(isi, sAtA, sAAi, 0.f);
    g_preT[i] = make_float4(iso, sAAt, sAAo, 0.f);
    g_post[0][i] = iso;  g_post[1][i] = isi;
    g_post[2][i] = sAAt; g_post[3][i] = sAtA;
    g_post[4][i] = sAAo; g_post[5][i] = sAAi;
}

// ---------------- round-1 fused SpMM over fp16 x: MLP-4 batched gather -------
__global__ void k_spmm3(int n) {
    int dir = blockIdx.y;
    int gw = (blockIdx.x * blockDim.x + threadIdx.x) >> 5;
    int lane = threadIdx.x & 31;
    if (gw >= n) return;
    const int* off = dir ? g_col_off : g_row_off;
    const int* nbr = dir ? g_csc_row : g_csr_col;
    const float4* pre = dir ? g_preT : g_preA;
    const float* post0 = dir ? g_post[1] : g_post[0];
    __half* out0 = g_Hh[dir];
    __half* out1 = dir ? g_uw : g_vz;
    __half* out2 = dir ? g_vz : g_uw;
    const uint32_t* xw = (const uint32_t*)g_xh;

    int s = off[gw], e = off[gw + 1];
    float a0x = 0.f, a0y = 0.f, a1x = 0.f, a1y = 0.f, a2x = 0.f, a2y = 0.f;
    for (int base = s; base < e; base += 32) {
        int idx = base + lane;
        int myn = 0;
        float4 mp = make_float4(0.f, 0.f, 0.f, 0.f);
        if (idx < e) {
            myn = __ldg(nbr + idx);
            mp = __ldg(pre + myn);
        }
        int cnt = min(32, e - base);
        for (int k = 0; k < cnt; k += 4) {
            int nd[4]; float p0[4], p1[4], p2[4]; uint32_t raw[4];
#pragma unroll
            for (int j = 0; j < 4; j++) {
                int kk = k + j;
                nd[j] = __shfl_sync(0xffffffffu, myn, kk);
                p0[j] = __shfl_sync(0xffffffffu, mp.x, kk);
                p1[j] = __shfl_sync(0xffffffffu, mp.y, kk);
                p2[j] = __shfl_sync(0xffffffffu, mp.z, kk);
            }
#pragma unroll
            for (int j = 0; j < 4; j++)
                raw[j] = __ldg(xw + (size_t)nd[j] * 32 + lane);
#pragma unroll
            for (int j = 0; j < 4; j++) {
                float2 f = __half22float2(*reinterpret_cast<__half2*>(&raw[j]));
                a0x = fmaf(p0[j], f.x, a0x); a0y = fmaf(p0[j], f.y, a0y);
                a1x = fmaf(p1[j], f.x, a1x); a1y = fmaf(p1[j], f.y, a1y);
                a2x = fmaf(p2[j], f.x, a2x); a2y = fmaf(p2[j], f.y, a2y);
            }
        }
    }
    float pp = post0[gw];
    *(__half2*)(out0 + (size_t)gw * F + lane * 2) = __floats2half2_rn(pp * a0x, pp * a0y);
    *(__half2*)(out1 + (size_t)gw * 128 + lane * 2) = __floats2half2_rn(a1x, a1y);
    *(__half2*)(out2 + (size_t)gw * 128 + 64 + lane * 2) = __floats2half2_rn(a2x, a2y);
}

// ---------------- round-2 fused SpMM: MLP-4 batched 256B gathers -------------
__global__ void k_spmm2(int n) {
    int dir = blockIdx.y;
    int gw = (blockIdx.x * blockDim.x + threadIdx.x) >> 5;
    int lane = threadIdx.x & 31;
    if (gw >= n) return;
    const int* off = dir ? g_col_off : g_row_off;
    const int* nbr = dir ? g_csc_row : g_csr_col;
    const uint2* in = (const uint2*)(dir ? g_vz : g_uw);

    int s = off[gw], e = off[gw + 1];
    float a0 = 0.f, a1 = 0.f, a2 = 0.f, a3 = 0.f;
    for (int base = s; base < e; base += 32) {
        int idx = base + lane;
        int myn = 0;
        float wt = 0.f;
        if (idx < e) { myn = __ldg(nbr + idx); wt = 1.f; }
        int cnt = min(32, e - base);
        for (int k = 0; k < cnt; k += 4) {
            int nd[4]; float wj[4]; uint2 raw[4];
#pragma unroll
            for (int j = 0; j < 4; j++) {
                int kk = k + j;
                nd[j] = __shfl_sync(0xffffffffu, myn, kk);
                wj[j] = __shfl_sync(0xffffffffu, wt, kk);
            }
#pragma unroll
            for (int j = 0; j < 4; j++)
                raw[j] = __ldg(in + (size_t)nd[j] * 32 + lane);
#pragma unroll
            for (int j = 0; j < 4; j++) {
                float2 f0 = __half22float2(*reinterpret_cast<__half2*>(&raw[j].x));
                float2 f1 = __half22float2(*reinterpret_cast<__half2*>(&raw[j].y));
                a0 = fmaf(wj[j], f0.x, a0); a1 = fmaf(wj[j], f0.y, a1);
                a2 = fmaf(wj[j], f1.x, a2); a3 = fmaf(wj[j], f1.y, a3);
            }
        }
    }
    bool partA = lane < 16;
    const float* post = dir ? (partA ? g_post[3] : g_post[5])
                            : (partA ? g_post[2] : g_post[4]);
    __half* outH = dir ? (partA ? g_Hh[3] : g_Hh[5])
                       : (partA ? g_Hh[2] : g_Hh[4]);
    float p = post[gw];
    int fbase = (lane & 15) * 4;
    __half2 o0 = __floats2half2_rn(p * a0, p * a1);
    __half2 o1 = __floats2half2_rn(p * a2, p * a3);
    uint2 st;
    st.x = *reinterpret_cast<uint32_t*>(&o0);
    st.y = *reinterpret_cast<uint32_t*>(&o1);
    *(uint2*)(outH + (size_t)gw * F + fbase) = st;
}

// ---------------- fp16 HMMA GEMM: out = 0.75*(sum H_m W_m + sum b_m) ---------
// H fp16 exact (A operand). W split Whi+Wlo fp16 (B operand), 2 MMAs per tile.
__device__ __forceinline__ void mma_f16(float* c, uint32_t a0, uint32_t a1,
                                        uint32_t a2, uint32_t a3,
                                        uint32_t b0, uint32_t b1) {
    asm volatile(
        "mma.sync.aligned.m16n8k16.row.col.f32.f16.f16.f32 "
        "{%0,%1,%2,%3}, {%4,%5,%6,%7}, {%8,%9}, {%0,%1,%2,%3};"
        : "+f"(c[0]), "+f"(c[1]), "+f"(c[2]), "+f"(c[3])
        : "r"(a0), "r"(a1), "r"(a2), "r"(a3), "r"(b0), "r"(b1));
}

#define LDH 72   // padded half stride: bank = (4g+t) pattern stays conflict-free

__global__ __launch_bounds__(256, 2) void k_gemm(
        const float* __restrict__ W0, const float* __restrict__ W1,
        const float* __restrict__ W2, const float* __restrict__ W3,
        const float* __restrict__ W4, const float* __restrict__ W5,
        const float* __restrict__ B0, const float* __restrict__ B1,
        const float* __restrict__ B2, const float* __restrict__ B3,
        const float* __restrict__ B4, const float* __restrict__ B5,
        float* __restrict__ out, int n) {
    __shared__ __half sH[64 * LDH];     // H tile [row][k]
    __shared__ __half sWhi[64 * LDH];   // W hi, TRANSPOSED [n][k]
    __shared__ __half sWlo[64 * LDH];   // W lo residual,   [n][k]
    __shared__ float sBias[64];
    const float* Ws[6] = {W0, W1, W2, W3, W4, W5};
    const float* Bs[6] = {B0, B1, B2, B3, B4, B5};

    int tid = threadIdx.x;
    int rowBase = blockIdx.x * 64;
    int w = tid >> 5;
    int lane = tid & 31;
    int g = lane >> 2;
    int t = lane & 3;
    int wr = (w & 1) * 32;
    int wc = (w >> 1) * 16;

    if (tid < 64) {
        float s = 0.f;
#pragma unroll
        for (int m = 0; m < 6; m++) s += __ldg(Bs[m] + tid);
        sBias[tid] = s;
    }

    float acc[2][2][4];
#pragma unroll
    for (int i = 0; i < 2; i++)
#pragma unroll
        for (int j = 0; j < 2; j++)
#pragma unroll
            for (int q = 0; q < 4; q++) acc[i][j][q] = 0.f;

#pragma unroll
    for (int m = 0; m < 6; m++) {
        const __half* Hm = g_Hh[m];
        const float* Wm = Ws[m];
        // H tile: 64 rows x 64 halves = 1024 uint2 (4 halves each)
#pragma unroll
        for (int it = 0; it < 4; it++) {
            int idx = tid + it * 256;
            int r = idx >> 4;
            int c4 = (idx & 15) << 2;          // half index, multiple of 4
            int gr = rowBase + r;
            uint2 raw = make_uint2(0u, 0u);
            if (gr < n) raw = __ldg((const uint2*)(Hm) + (size_t)gr * 16 + (idx & 15));
            *(uint2*)(&sH[r * LDH + c4]) = raw;
        }
        // W: 4096 fp32 -> hi/lo fp16, transposed [n][k]
#pragma unroll
        for (int it = 0; it < 16; it++) {
            int idx = tid + it * 256;
            int k = idx >> 6;
            int nn = idx & 63;
            float wv = __ldg(Wm + idx);
            __half hi = __float2half_rn(wv);
            __half lo = __float2half_rn(wv - __half2float(hi));
            sWhi[nn * LDH + k] = hi;
            sWlo[nn * LDH + k] = lo;
        }
        __syncthreads();

#pragma unroll
        for (int kk = 0; kk < 64; kk += 16) {
            uint32_t a[2][4];
#pragma unroll
            for (int mt = 0; mt < 2; mt++) {
                int rbase = wr + mt * 16;
                a[mt][0] = *(const uint32_t*)(&sH[(rbase + g) * LDH + kk + 2 * t]);
                a[mt][1] = *(const uint32_t*)(&sH[(rbase + g + 8) * LDH + kk + 2 * t]);
                a[mt][2] = *(const uint32_t*)(&sH[(rbase + g) * LDH + kk + 2 * t + 8]);
                a[mt][3] = *(const uint32_t*)(&sH[(rbase + g + 8) * LDH + kk + 2 * t + 8]);
            }
            uint32_t bh[2][2], bl[2][2];
#pragma unroll
            for (int nt = 0; nt < 2; nt++) {
                int nbase = wc + nt * 8;
                bh[nt][0] = *(const uint32_t*)(&sWhi[(nbase + g) * LDH + kk + 2 * t]);
                bh[nt][1] = *(const uint32_t*)(&sWhi[(nbase + g) * LDH + kk + 2 * t + 8]);
                bl[nt][0] = *(const uint32_t*)(&sWlo[(nbase + g) * LDH + kk + 2 * t]);
                bl[nt][1] = *(const uint32_t*)(&sWlo[(nbase + g) * LDH + kk + 2 * t + 8]);
            }
#pragma unroll
            for (int mt = 0; mt < 2; mt++)
#pragma unroll
                for (int nt = 0; nt < 2; nt++) {
                    mma_f16(acc[mt][nt], a[mt][0], a[mt][1], a[mt][2], a[mt][3],
                            bl[nt][0], bl[nt][1]);
                    mma_f16(acc[mt][nt], a[mt][0], a[mt][1], a[mt][2], a[mt][3],
                            bh[nt][0], bh[nt][1]);
                }
        }
        __syncthreads();
    }

#pragma unroll
    for (int mt = 0; mt < 2; mt++) {
#pragma unroll
        for (int nt = 0; nt < 2; nt++) {
            int col = wc + nt * 8 + 2 * t;
            float bx = sBias[col], by = sBias[col + 1];
            int r1 = rowBase + wr + mt * 16 + g;
            int r2 = r1 + 8;
            if (r1 < n) {
                float2 o;
                o.x = 0.75f * (acc[mt][nt][0] + bx);
                o.y = 0.75f * (acc[mt][nt][1] + by);
                *(float2*)(out + (size_t)r1 * 64 + col) = o;
            }
            if (r2 < n) {
                float2 o;
                o.x = 0.75f * (acc[mt][nt][2] + bx);
                o.y = 0.75f * (acc[mt][nt][3] + by);
                *(float2*)(out + (size_t)r2 * 64 + col) = o;
            }
        }
    }
}

// ---------------- launcher ----------------
extern "C" void kernel_launch(void* const* d_in, const int* in_sizes, int n_in,
                              void* d_out, int out_size) {
    const float* x = (const float*)d_in[0];
    const int* ei = (const int*)d_in[1];
    const float* W0 = (const float*)d_in[2],  *B0 = (const float*)d_in[3];
    const float* W1 = (const float*)d_in[4],  *B1 = (const float*)d_in[5];
    const float* W2 = (const float*)d_in[6],  *B2 = (const float*)d_in[7];
    const float* W3 = (const float*)d_in[8],  *B3 = (const float*)d_in[9];
    const float* W4 = (const float*)d_in[10], *B4 = (const float*)d_in[11];
    const float* W5 = (const float*)d_in[12], *B5 = (const float*)d_in[13];
    float* out = (float*)d_out;

    int n = in_sizes[0] / F;
    int E = in_sizes[1] / 2;
    if (n > NN) n = NN;
    if (E > EE) E = EE;

    int nb = (n + 255) / 256;
    int eb = (E + 255) / 256;
    int pb = (n + SCAN_B - 1) / SCAN_B;
    int xw = n * 32;                       // half2 words in x

    k_xhalf<<<(xw + 255) / 256, 256>>>(x, xw, n);
    k_hist<<<eb, 256>>>(ei, E);
    k_scan_part<<<dim3(pb, 2), 256>>>(n);
    k_scan_mid<<<1, 128>>>(pb);
    k_scan_final<<<dim3(pb, 2), SCAN_B>>>(n, pb);
    k_scatter<<<eb, 256>>>(ei, E);
    k_degspmv<<<dim3(nb, 2), 256>>>(n);
    k_scales<<<nb, 256>>>(n);

    int sb = (n + 7) / 8;   // warp-per-node, 8 warps/block
    k_spmm3<<<dim3(sb, 2), 256>>>(n);
    k_spmm2<<<dim3(sb, 2), 256>>>(n);

    int gb = (n + 63) / 64;
    k_gemm<<<gb, 256>>>(W0, W1, W2, W3, W4, W5,
                        B0, B1, B2, B3, B4, B5, out, n);
}

// round 11
// speedup vs baseline: 1.4463x; 1.0948x over previous
#include <cuda_runtime.h>
#include <cuda_fp16.h>
#include <cstdint>

#define NN 100000
#define EE 1600000
#define F 64
#define SCAN_B 1024
#define MAXPB 128   // ceil(NN/1024) = 98 <= 128

// ---------------- device scratch (static: allocation-guard safe) ----------------
__device__ int   g_cnt_row[NN];
__device__ int   g_cnt_col[NN];
__device__ int2  g_cntp[NN];      // packed {cnt_row, cnt_col}
__device__ int   g_row_off[NN + 1];
__device__ int   g_col_off[NN + 1];
__device__ int   g_cur_row[NN];
__device__ int   g_cur_col[NN];
__device__ int   g_part[2][MAXPB];
__device__ int   g_partscan[2][MAXPB + 1];
__device__ int   g_csr_col[EE];   // neighbors (col ids) grouped by row  -> Av
__device__ int   g_csc_row[EE];   // neighbors (row ids) grouped by col  -> Atv
__device__ float g_Avdin[NN], g_Avdout[NN], g_Atvdout[NN], g_Atvdin[NN];
__device__ float4 g_preA[NN];     // {isi, sAtA, sAAi, 0} pre-scales for round-1 Av
__device__ float4 g_preT[NN];     // {iso, sAAt, sAAo, 0} pre-scales for round-1 Atv
__device__ float g_post[6][NN];   // 0:iso 1:isi 2:sAAt 3:sAtA 4:sAAo 5:sAAi
__device__ __half g_xh[(size_t)NN * F];        // fp16 copy of x (128B/row)
__device__ __half g_uw[(size_t)(NN + 1) * 128];  // [u | w]; row NN stays zero
__device__ __half g_vz[(size_t)(NN + 1) * 128];  // [v | z]; row NN stays zero
__device__ __half g_Hh[6][(size_t)NN * F];     // A_x, At_x, AAt_x, AtA_x, AA_x, AtAt_x

// ---------------- x -> fp16 copy, fused with counter zeroing ----------------
__global__ void k_xhalf(const float* __restrict__ x, int total32, int n) {
    int i = blockIdx.x * blockDim.x + threadIdx.x;
    if (i < n) { g_cnt_row[i] = 0; g_cnt_col[i] = 0; }
    if (i < total32) {
        float2 f = __ldg((const float2*)x + i);
        *((__half2*)g_xh + i) = __floats2half2_rn(f.x, f.y);
    }
}

__global__ void k_hist(const int* __restrict__ ei, int E) {
    int e = blockIdx.x * blockDim.x + threadIdx.x;
    if (e < E) {
        atomicAdd(&g_cnt_row[ei[e]], 1);
        atomicAdd(&g_cnt_col[ei[E + e]], 1);
    }
}

// -------- multi-block exclusive scan: phase 1, per-block partial sums --------
__global__ void k_scan_part(int n) {
    int dir = blockIdx.y;
    const int* cnt = dir ? g_cnt_col : g_cnt_row;
    __shared__ int sh[256];
    int tid = threadIdx.x;
    int base = blockIdx.x * SCAN_B;
    int s = 0;
#pragma unroll
    for (int j = 0; j < 4; j++) {
        int i = base + tid + j * 256;
        if (i < n) s += cnt[i];
    }
    sh[tid] = s;
    __syncthreads();
    for (int d = 128; d > 0; d >>= 1) {
        if (tid < d) sh[tid] += sh[tid + d];
        __syncthreads();
    }
    if (tid == 0) g_part[dir][blockIdx.x] = sh[0];
}

// -------- phase 2: single block scans the <=128 partials for both dirs -------
__global__ void k_scan_mid(int pb) {
    __shared__ int sh[128];
    int tid = threadIdx.x;
    for (int dir = 0; dir < 2; dir++) {
        int v = (tid < pb) ? g_part[dir][tid] : 0;
        sh[tid] = v;
        __syncthreads();
        for (int d = 1; d < 128; d <<= 1) {
            int add = (tid >= d) ? sh[tid - d] : 0;
            __syncthreads();
            sh[tid] += add;
            __syncthreads();
        }
        if (tid < pb) g_partscan[dir][tid] = sh[tid] - v;   // exclusive
        if (tid == 0) g_partscan[dir][pb] = sh[127];        // total
        __syncthreads();
    }
}

// -------- phase 3: per-block scan + base; init cursors; pack counts ----------
__global__ void k_scan_final(int n, int pb) {
    int dir = blockIdx.y;
    const int* cnt = dir ? g_cnt_col : g_cnt_row;
    int* off = dir ? g_col_off : g_row_off;
    int* cur = dir ? g_cur_col : g_cur_row;
    __shared__ int sh[SCAN_B];
    int tid = threadIdx.x;
    int i = blockIdx.x * SCAN_B + tid;
    int v = (i < n) ? cnt[i] : 0;
    sh[tid] = v;
    __syncthreads();
    for (int d = 1; d < SCAN_B; d <<= 1) {
        int add = (tid >= d) ? sh[tid - d] : 0;
        __syncthreads();
        sh[tid] += add;
        __syncthreads();
    }
    if (i < n) {
        int o = g_partscan[dir][blockIdx.x] + sh[tid] - v;  // exclusive
        off[i] = o;
        cur[i] = o;
        if (dir == 0) {
            // pack {cnt_row, cnt_col} for degspmv's single-sector lookups
            g_cntp[i] = make_int2(v, g_cnt_col[i]);
        }
    }
    if (blockIdx.x == 0 && tid == 0) off[n] = g_partscan[dir][pb];
}

__global__ void k_scatter(const int* __restrict__ ei, int E) {
    int e = blockIdx.x * blockDim.x + threadIdx.x;
    if (e < E) {
        int r = ei[e], c = ei[E + e];
        int p = atomicAdd(&g_cur_row[r], 1);
        g_csr_col[p] = c;
        int q = atomicAdd(&g_cur_col[c], 1);
        g_csc_row[q] = r;
    }
}

// ---------------- scalar degree SpMVs, MLP-4, packed count lookups -----------
__global__ void k_degspmv(int n) {
    int dir = blockIdx.y;
    int i = blockIdx.x * blockDim.x + threadIdx.x;
    if (i >= n) return;
    const int* off = dir ? g_col_off : g_row_off;
    const int* nbr = dir ? g_csc_row : g_csr_col;
    // dir0 (Av):  oA = sum cnt_col(nb) [=d_in], oB = sum cnt_row(nb) [=d_out]
    // dir1 (Atv): oA = sum cnt_row(nb) [=d_out], oB = sum cnt_col(nb) [=d_in]
    float* oA = dir ? g_Atvdout : g_Avdin;
    float* oB = dir ? g_Atvdin  : g_Avdout;
    int s = off[i], e = off[i + 1];
    int sa = 0, sb = 0;
    int j = s;
    for (; j + 4 <= e; j += 4) {
        int n0 = __ldg(nbr + j + 0);
        int n1 = __ldg(nbr + j + 1);
        int n2 = __ldg(nbr + j + 2);
        int n3 = __ldg(nbr + j + 3);
        int2 p0 = __ldg(g_cntp + n0);
        int2 p1 = __ldg(g_cntp + n1);
        int2 p2 = __ldg(g_cntp + n2);
        int2 p3 = __ldg(g_cntp + n3);
        if (dir) {
            sa += (p0.x + p1.x) + (p2.x + p3.x);
            sb += (p0.y + p1.y) + (p2.y + p3.y);
        } else {
            sa += (p0.y + p1.y) + (p2.y + p3.y);
            sb += (p0.x + p1.x) + (p2.x + p3.x);
        }
    }
    for (; j < e; j++) {
        int nb = __ldg(nbr + j);
        int2 p = __ldg(g_cntp + nb);
        sa += dir ? p.x : p.y;
        sb += dir ? p.y : p.x;
    }
    oA[i] = (float)sa;
    oB[i] = (float)sb;
}

__device__ __forceinline__ float invsq(float d) {
    return d > 0.f ? 1.0f / sqrtf(d) : 0.0f;
}

__global__ void k_scales(int n) {
    int i = blockIdx.x * blockDim.x + threadIdx.x;
    if (i >= n) return;
    float iso  = invsq((float)g_cnt_row[i]);
    float isi  = invsq((float)g_cnt_col[i]);
    float sAAt = invsq(g_Avdin[i]);
    float sAtA = invsq(g_Atvdout[i]);
    float sAAo = invsq(g_Avdout[i]);
    float sAAi = invsq(g_Atvdin[i]);
    g_preA[i] = make_float4(isi, sAtA, sAAi, 0.f);
    g_preT[i] = make_float4(iso, sAAt, sAAo, 0.f);
    g_post[0][i] = iso;  g_post[1][i] = isi;
    g_post[2][i] = sAAt; g_post[3][i] = sAtA;
    g_post[4][i] = sAAo; g_post[5][i] = sAAi;
}

// ---------------- round-1 fused SpMM over fp16 x: MLP-4 batched gather -------
__global__ void k_spmm3(int n) {
    int dir = blockIdx.y;
    int gw = (blockIdx.x * blockDim.x + threadIdx.x) >> 5;
    int lane = threadIdx.x & 31;
    if (gw >= n) return;
    const int* off = dir ? g_col_off : g_row_off;
    const int* nbr = dir ? g_csc_row : g_csr_col;
    const float4* pre = dir ? g_preT : g_preA;
    const float* post0 = dir ? g_post[1] : g_post[0];
    __half* out0 = g_Hh[dir];
    __half* out1 = dir ? g_uw : g_vz;
    __half* out2 = dir ? g_vz : g_uw;
    const uint32_t* xw = (const uint32_t*)g_xh;

    int s = off[gw], e = off[gw + 1];
    float a0x = 0.f, a0y = 0.f, a1x = 0.f, a1y = 0.f, a2x = 0.f, a2y = 0.f;
    for (int base = s; base < e; base += 32) {
        int idx = base + lane;
        int myn = 0;
        float4 mp = make_float4(0.f, 0.f, 0.f, 0.f);
        if (idx < e) {
            myn = __ldg(nbr + idx);
            mp = __ldg(pre + myn);
        }
        int cnt = min(32, e - base);
        for (int k = 0; k < cnt; k += 4) {
            int nd[4]; float p0[4], p1[4], p2[4]; uint32_t raw[4];
#pragma unroll
            for (int j = 0; j < 4; j++) {
                int kk = k + j;
                nd[j] = __shfl_sync(0xffffffffu, myn, kk);
                p0[j] = __shfl_sync(0xffffffffu, mp.x, kk);
                p1[j] = __shfl_sync(0xffffffffu, mp.y, kk);
                p2[j] = __shfl_sync(0xffffffffu, mp.z, kk);
            }
#pragma unroll
            for (int j = 0; j < 4; j++)
                raw[j] = __ldg(xw + (size_t)nd[j] * 32 + lane);
#pragma unroll
            for (int j = 0; j < 4; j++) {
                float2 f = __half22float2(*reinterpret_cast<__half2*>(&raw[j]));
                a0x = fmaf(p0[j], f.x, a0x); a0y = fmaf(p0[j], f.y, a0y);
                a1x = fmaf(p1[j], f.x, a1x); a1y = fmaf(p1[j], f.y, a1y);
                a2x = fmaf(p2[j], f.x, a2x); a2y = fmaf(p2[j], f.y, a2y);
            }
        }
    }
    float pp = post0[gw];
    *(__half2*)(out0 + (size_t)gw * F + lane * 2) = __floats2half2_rn(pp * a0x, pp * a0y);
    *(__half2*)(out1 + (size_t)gw * 128 + lane * 2) = __floats2half2_rn(a1x, a1y);
    *(__half2*)(out2 + (size_t)gw * 128 + 64 + lane * 2) = __floats2half2_rn(a2x, a2y);
}

// ---------------- round-2 fused SpMM: MLP-4, fp16 depth-4 partials -----------
// Invalid tail lanes index the reserved zero row (n) — no weight shuffle needed.
__global__ void k_spmm2(int n) {
    int dir = blockIdx.y;
    int gw = (blockIdx.x * blockDim.x + threadIdx.x) >> 5;
    int lane = threadIdx.x & 31;
    if (gw >= n) return;
    const int* off = dir ? g_col_off : g_row_off;
    const int* nbr = dir ? g_csc_row : g_csr_col;
    const uint2* in = (const uint2*)(dir ? g_vz : g_uw);

    int s = off[gw], e = off[gw + 1];
    float a0 = 0.f, a1 = 0.f, a2 = 0.f, a3 = 0.f;
    for (int base = s; base < e; base += 32) {
        int idx = base + lane;
        int myn = (idx < e) ? __ldg(nbr + idx) : n;   // zero row for tail lanes
        int cnt = min(32, e - base);
        for (int k = 0; k < cnt; k += 4) {
            int nd[4]; uint2 raw[4];
#pragma unroll
            for (int j = 0; j < 4; j++)
                nd[j] = __shfl_sync(0xffffffffu, myn, k + j);
#pragma unroll
            for (int j = 0; j < 4; j++)
                raw[j] = __ldg(in + (size_t)nd[j] * 32 + lane);
            // depth-4 fp16 partial sums, flushed to fp32 per batch
            __half2 s0 = *reinterpret_cast<__half2*>(&raw[0].x);
            __half2 s1 = *reinterpret_cast<__half2*>(&raw[0].y);
#pragma unroll
            for (int j = 1; j < 4; j++) {
                s0 = __hadd2(s0, *reinterpret_cast<__half2*>(&raw[j].x));
                s1 = __hadd2(s1, *reinterpret_cast<__half2*>(&raw[j].y));
            }
            float2 f0 = __half22float2(s0);
            float2 f1 = __half22float2(s1);
            a0 += f0.x; a1 += f0.y; a2 += f1.x; a3 += f1.y;
        }
    }
    bool partA = lane < 16;
    const float* post = dir ? (partA ? g_post[3] : g_post[5])
                            : (partA ? g_post[2] : g_post[4]);
    __half* outH = dir ? (partA ? g_Hh[3] : g_Hh[5])
                       : (partA ? g_Hh[2] : g_Hh[4]);
    float p = post[gw];
    int fbase = (lane & 15) * 4;
    __half2 o0 = __floats2half2_rn(p * a0, p * a1);
    __half2 o1 = __floats2half2_rn(p * a2, p * a3);
    uint2 st;
    st.x = *reinterpret_cast<uint32_t*>(&o0);
    st.y = *reinterpret_cast<uint32_t*>(&o1);
    *(uint2*)(outH + (size_t)gw * F + fbase) = st;
}

// ---------------- fp16 HMMA GEMM: out = 0.75*(sum H_m W_m + sum b_m) ---------
__device__ __forceinline__ void mma_f16(float* c, uint32_t a0, uint32_t a1,
                                        uint32_t a2, uint32_t a3,
                                        uint32_t b0, uint32_t b1) {
    asm volatile(
        "mma.sync.aligned.m16n8k16.row.col.f32.f16.f16.f32 "
        "{%0,%1,%2,%3}, {%4,%5,%6,%7}, {%8,%9}, {%0,%1,%2,%3};"
        : "+f"(c[0]), "+f"(c[1]), "+f"(c[2]), "+f"(c[3])
        : "r"(a0), "r"(a1), "r"(a2), "r"(a3), "r"(b0), "r"(b1));
}

#define LDH 72   // padded half stride: bank = (4g+t) pattern stays conflict-free

__global__ __launch_bounds__(256, 2) void k_gemm(
        const float* __restrict__ W0, const float* __restrict__ W1,
        const float* __restrict__ W2, const float* __restrict__ W3,
        const float* __restrict__ W4, const float* __restrict__ W5,
        const float* __restrict__ B0, const float* __restrict__ B1,
        const float* __restrict__ B2, const float* __restrict__ B3,
        const float* __restrict__ B4, const float* __restrict__ B5,
        float* __restrict__ out, int n) {
    __shared__ __half sH[64 * LDH];     // H tile [row][k]
    __shared__ __half sWhi[64 * LDH];   // W hi, TRANSPOSED [n][k]
    __shared__ __half sWlo[64 * LDH];   // W lo residual,   [n][k]
    __shared__ float sBias[64];
    const float* Ws[6] = {W0, W1, W2, W3, W4, W5};
    const float* Bs[6] = {B0, B1, B2, B3, B4, B5};

    int tid = threadIdx.x;
    int rowBase = blockIdx.x * 64;
    int w = tid >> 5;
    int lane = tid & 31;
    int g = lane >> 2;
    int t = lane & 3;
    int wr = (w & 1) * 32;
    int wc = (w >> 1) * 16;

    if (tid < 64) {
        float s = 0.f;
#pragma unroll
        for (int m = 0; m < 6; m++) s += __ldg(Bs[m] + tid);
        sBias[tid] = s;
    }

    float acc[2][2][4];
#pragma unroll
    for (int i = 0; i < 2; i++)
#pragma unroll
        for (int j = 0; j < 2; j++)
#pragma unroll
            for (int q = 0; q < 4; q++) acc[i][j][q] = 0.f;

#pragma unroll
    for (int m = 0; m < 6; m++) {
        const __half* Hm = g_Hh[m];
        const float* Wm = Ws[m];
        // H tile: 64 rows x 64 halves = 1024 uint2 (4 halves each)
#pragma unroll
        for (int it = 0; it < 4; it++) {
            int idx = tid + it * 256;
            int r = idx >> 4;
            int c4 = (idx & 15) << 2;          // half index, multiple of 4
            int gr = rowBase + r;
            uint2 raw = make_uint2(0u, 0u);
            if (gr < n) raw = __ldg((const uint2*)(Hm) + (size_t)gr * 16 + (idx & 15));
            *(uint2*)(&sH[r * LDH + c4]) = raw;
        }
        // W: 4096 fp32 -> hi/lo fp16, transposed [n][k]
#pragma unroll
        for (int it = 0; it < 16; it++) {
            int idx = tid + it * 256;
            int k = idx >> 6;
            int nn = idx & 63;
            float wv = __ldg(Wm + idx);
            __half hi = __float2half_rn(wv);
            __half lo = __float2half_rn(wv - __half2float(hi));
            sWhi[nn * LDH + k] = hi;
            sWlo[nn * LDH + k] = lo;
        }
        __syncthreads();

#pragma unroll
        for (int kk = 0; kk < 64; kk += 16) {
            uint32_t a[2][4];
#pragma unroll
            for (int mt = 0; mt < 2; mt++) {
                int rbase = wr + mt * 16;
                a[mt][0] = *(const uint32_t*)(&sH[(rbase + g) * LDH + kk + 2 * t]);
                a[mt][1] = *(const uint32_t*)(&sH[(rbase + g + 8) * LDH + kk + 2 * t]);
                a[mt][2] = *(const uint32_t*)(&sH[(rbase + g) * LDH + kk + 2 * t + 8]);
                a[mt][3] = *(const uint32_t*)(&sH[(rbase + g + 8) * LDH + kk + 2 * t + 8]);
            }
            uint32_t bh[2][2], bl[2][2];
#pragma unroll
            for (int nt = 0; nt < 2; nt++) {
                int nbase = wc + nt * 8;
                bh[nt][0] = *(const uint32_t*)(&sWhi[(nbase + g) * LDH + kk + 2 * t]);
                bh[nt][1] = *(const uint32_t*)(&sWhi[(nbase + g) * LDH + kk + 2 * t + 8]);
                bl[nt][0] = *(const uint32_t*)(&sWlo[(nbase + g) * LDH + kk + 2 * t]);
                bl[nt][1] = *(const uint32_t*)(&sWlo[(nbase + g) * LDH + kk + 2 * t + 8]);
            }
#pragma unroll
            for (int mt = 0; mt < 2; mt++)
#pragma unroll
                for (int nt = 0; nt < 2; nt++) {
                    mma_f16(acc[mt][nt], a[mt][0], a[mt][1], a[mt][2], a[mt][3],
                            bl[nt][0], bl[nt][1]);
                    mma_f16(acc[mt][nt], a[mt][0], a[mt][1], a[mt][2], a[mt][3],
                            bh[nt][0], bh[nt][1]);
                }
        }
        __syncthreads();
    }

#pragma unroll
    for (int mt = 0; mt < 2; mt++) {
#pragma unroll
        for (int nt = 0; nt < 2; nt++) {
            int col = wc + nt * 8 + 2 * t;
            float bx = sBias[col], by = sBias[col + 1];
            int r1 = rowBase + wr + mt * 16 + g;
            int r2 = r1 + 8;
            if (r1 < n) {
                float2 o;
                o.x = 0.75f * (acc[mt][nt][0] + bx);
                o.y = 0.75f * (acc[mt][nt][1] + by);
                *(float2*)(out + (size_t)r1 * 64 + col) = o;
            }
            if (r2 < n) {
                float2 o;
                o.x = 0.75f * (acc[mt][nt][2] + bx);
                o.y = 0.75f * (acc[mt][nt][3] + by);
                *(float2*)(out + (size_t)r2 * 64 + col) = o;
            }
        }
    }
}

// ---------------- launcher ----------------
extern "C" void kernel_launch(void* const* d_in, const int* in_sizes, int n_in,
                              void* d_out, int out_size) {
    const float* x = (const float*)d_in[0];
    const int* ei = (const int*)d_in[1];
    const float* W0 = (const float*)d_in[2],  *B0 = (const float*)d_in[3];
    const float* W1 = (const float*)d_in[4],  *B1 = (const float*)d_in[5];
    const float* W2 = (const float*)d_in[6],  *B2 = (const float*)d_in[7];
    const float* W3 = (const float*)d_in[8],  *B3 = (const float*)d_in[9];
    const float* W4 = (const float*)d_in[10], *B4 = (const float*)d_in[11];
    const float* W5 = (const float*)d_in[12], *B5 = (const float*)d_in[13];
    float* out = (float*)d_out;

    int n = in_sizes[0] / F;
    int E = in_sizes[1] / 2;
    if (n > NN) n = NN;
    if (E > EE) E = EE;

    int nb = (n + 255) / 256;
    int eb = (E + 255) / 256;
    int pb = (n + SCAN_B - 1) / SCAN_B;
    int xw = n * 32;                       // half2 words in x

    k_xhalf<<<(xw + 255) / 256, 256>>>(x, xw, n);
    k_hist<<<eb, 256>>>(ei, E);
    k_scan_part<<<dim3(pb, 2), 256>>>(n);
    k_scan_mid<<<1, 128>>>(pb);
    k_scan_final<<<dim3(pb, 2), SCAN_B>>>(n, pb);
    k_scatter<<<eb, 256>>>(ei, E);
    k_degspmv<<<dim3(nb, 2), 256>>>(n);
    k_scales<<<nb, 256>>>(n);

    int sb = (n + 7) / 8;   // warp-per-node, 8 warps/block
    k_spmm3<<<dim3(sb, 2), 256>>>(n);
    k_spmm2<<<dim3(sb, 2), 256>>>(n);

    int gb = (n + 63) / 64;
    k_gemm<<<gb, 256>>>(W0, W1, W2, W3, W4, W5,
                        B0, B1, B2, B3, B4, B5, out, n);
}